// round 1
// baseline (speedup 1.0000x reference)
#include <cuda_runtime.h>
#include <cstdint>
#include <cstdio>

// ---------------- problem constants ----------------
#define T_SEQ 512
#define B_SZ  256
#define IN_D  64
#define H_D   128
#define G4    512   // 4*H
#define L_N   5

// ping-pong inter-layer activation buffers (scratch via __device__ globals)
__device__ float g_bufA[T_SEQ * B_SZ * H_D];
__device__ float g_bufB[T_SEQ * B_SZ * H_D];

// ---------------- f32x2 packed FMA helpers ----------------
__device__ __forceinline__ void fma2(unsigned long long &acc,
                                     unsigned long long a,
                                     unsigned long long b) {
    asm("fma.rn.f32x2 %0, %1, %2, %3;" : "=l"(acc) : "l"(a), "l"(b), "l"(acc));
}
__device__ __forceinline__ unsigned long long pack2(float lo, float hi) {
    unsigned long long r;
    asm("mov.b64 %0, {%1, %2};" : "=l"(r) : "f"(lo), "f"(hi));
    return r;
}
__device__ __forceinline__ float2 unpack2(unsigned long long v) {
    float2 f;
    asm("mov.b64 {%0, %1}, %2;" : "=f"(f.x), "=f"(f.y) : "l"(v));
    return f;
}
__device__ __forceinline__ float sigmoidf_(float x) {
    return 1.0f / (1.0f + expf(-x));
}

// ============================================================================
// Fused LSTM layer kernel (persistent over all T timesteps).
//
// Grid: 128 CTAs, cluster of 4 (x-major). Cluster c handles batch rows
// [8c, 8c+8). Within a cluster, CTA rank r owns gate-column slice
// j in [32r, 32r+32) for all 4 gates (i,f,g,o), i.e. 128 gate rows.
//
// gates[b, gr] = dot(concat(x[t,b,:], h[t-1,b,:]), concat(W_ih[gr,:],W_hh[gr,:]))
//                + b_ih[gr] + b_hh[gr]
//
// Weights live in REGISTERS (each thread holds half the K-dim of one gate
// row, packed as f32x2). xh = [x|h] lives in smem (double buffered);
// every LDS in the hot loop is a warp-uniform broadcast.
// h exchange between the 4 CTAs goes through DSMEM st.shared::cluster,
// ordered by one barrier.cluster per timestep.
// ============================================================================
template<int KIN>
__global__ void __launch_bounds__(256, 1) __cluster_dims__(4, 1, 1)
lstm_layer_persist(const float* __restrict__ in,   // [T, B, KIN]
                   float* __restrict__ out,         // [T, B, H]
                   const float* __restrict__ Wih,   // [4H, KIN]
                   const float* __restrict__ Whh,   // [4H, H]
                   const float* __restrict__ bih,   // [4H]
                   const float* __restrict__ bhh)   // [4H]
{
    constexpr int K   = KIN + H_D;   // 192 or 256
    constexpr int K2  = K / 2;       // per-thread K slice: 96 or 128
    constexpr int NW2 = K2 / 2;      // f32x2 regs per thread: 48 or 64

    __shared__ float xh[2][8][K];        // double-buffered [x | h]
    __shared__ float gbuf[2][8][128];    // partial gate sums [kh][b][rr]

    const int tid  = threadIdx.x;
    const int lane = tid & 31;
    const int w    = tid >> 5;
    const int kh   = w & 1;                     // K-half this warp covers
    const int rr   = ((w >> 1) << 5) + lane;    // local gate row 0..127

    uint32_t rank;
    asm("mov.u32 %0, %%cluster_ctarank;" : "=r"(rank));
    const int cid = blockIdx.x >> 2;
    const int b0  = cid * 8;

    // compute-phase identity: global gate row for this thread's W slice
    const int gq   = rr >> 5;                   // gate 0..3 (i,f,g,o)
    const int jl_w = rr & 31;
    const int gr   = gq * H_D + (int)rank * 32 + jl_w;

    // ---- load this thread's W slice into registers (f32x2 packed over k) ----
    unsigned long long W2[NW2];
#pragma unroll
    for (int i = 0; i < NW2; i++) {
        const int k = kh * K2 + 2 * i;
        const float f0 = (k     < KIN) ? Wih[gr * KIN + k]
                                       : Whh[gr * H_D + (k     - KIN)];
        const float f1 = (k + 1 < KIN) ? Wih[gr * KIN + k + 1]
                                       : Whh[gr * H_D + (k + 1 - KIN)];
        W2[i] = pack2(f0, f1);
    }

    // output-phase identity: thread owns element (ob, oj)
    const int ob    = tid >> 5;                 // batch row 0..7
    const int oj    = tid & 31;                 // local j
    const int jglob = (int)rank * 32 + oj;      // global hidden index
    float bsum[4];
#pragma unroll
    for (int g = 0; g < 4; g++) {
        const int row = g * H_D + jglob;
        bsum[g] = bih[row] + bhh[row];
    }
    float c_state = 0.0f;

    // ---- prologue: xh[0] = [x(t=0) | h=0] ----
    for (int idx = tid; idx < 8 * KIN; idx += 256) {
        const int b = idx / KIN, k = idx % KIN;
        xh[0][b][k] = in[(size_t)(b0 + b) * KIN + k];
    }
    for (int idx = tid; idx < 8 * H_D; idx += 256) {
        const int b = idx / H_D, j = idx % H_D;
        xh[0][b][KIN + j] = 0.0f;
    }
    __syncthreads();

    for (int t = 0; t < T_SEQ; t++) {
        const int cur = t & 1;
        const int nxt = cur ^ 1;

        // ---- prefetch x[t+1] into registers (overlaps with the dots) ----
        float4 pf4;
        float2 pf2;
        const bool havenext = (t + 1 < T_SEQ);
        const int pb = tid >> 5;                                // row 0..7
        const int pk = (KIN == 128) ? (lane * 4) : (lane * 2);  // col start
        if (havenext) {
            const float* src = in + ((size_t)(t + 1) * B_SZ + b0) * KIN;
            if (KIN == 128) pf4 = *(const float4*)(src + pb * KIN + pk);
            else            pf2 = *(const float2*)(src + pb * KIN + pk);
        }

        // ---- dot products: acc[b] over this thread's K-half ----
        unsigned long long acc[8];
#pragma unroll
        for (int b = 0; b < 8; b++) acc[b] = 0ull;
#pragma unroll
        for (int kk = 0; kk < K2 / 4; kk++) {
#pragma unroll
            for (int b = 0; b < 8; b++) {
                // warp-uniform broadcast load of 4 xh floats (2 f32x2 pairs)
                ulonglong2 v = *(const ulonglong2*)(&xh[cur][b][kh * K2 + 4 * kk]);
                fma2(acc[b], v.x, W2[2 * kk]);
                fma2(acc[b], v.y, W2[2 * kk + 1]);
            }
        }
#pragma unroll
        for (int b = 0; b < 8; b++) {
            const float2 s = unpack2(acc[b]);
            gbuf[kh][b][rr] = s.x + s.y;   // conflict-free: lanes -> consecutive rr
        }
        __syncthreads();

        // ---- combine partials, activations, state update ----
        float gv[4];
#pragma unroll
        for (int g = 0; g < 4; g++)
            gv[g] = bsum[g] + gbuf[0][ob][g * 32 + oj] + gbuf[1][ob][g * 32 + oj];
        const float ig = sigmoidf_(gv[0]);
        const float fg = sigmoidf_(gv[1]);
        const float gg = tanhf(gv[2]);
        const float og = sigmoidf_(gv[3]);
        c_state = fg * c_state + ig * gg;
        const float h = og * tanhf(c_state);

        // ---- publish h: own smem, 3 peer CTAs via DSMEM, and global out ----
        xh[nxt][ob][KIN + jglob] = h;
        const uint32_t laddr =
            (uint32_t)__cvta_generic_to_shared(&xh[nxt][ob][KIN + jglob]);
#pragma unroll
        for (int pr = 0; pr < 4; pr++) {
            if (pr != (int)rank) {
                asm volatile(
                    "{ .reg .b32 ra;\n\t"
                    "  mapa.shared::cluster.u32 ra, %0, %1;\n\t"
                    "  st.shared::cluster.f32 [ra], %2; }"
                    :: "r"(laddr), "r"(pr), "f"(h) : "memory");
            }
        }
        out[((size_t)t * B_SZ + b0 + ob) * H_D + jglob] = h;   // coalesced

        // ---- stage prefetched x[t+1] into next buffer ----
        if (havenext) {
            if (KIN == 128) *(float4*)(&xh[nxt][pb][pk]) = pf4;
            else            *(float2*)(&xh[nxt][pb][pk]) = pf2;
        }

        // ---- cluster barrier: orders all h publications for step t+1 ----
        asm volatile("barrier.cluster.arrive.aligned;" ::: "memory");
        asm volatile("barrier.cluster.wait.aligned;"   ::: "memory");
    }
}

// ============================================================================
// kernel_launch: 5 sequential layer kernels (graph-capturable, no allocs)
// ============================================================================
extern "C" void kernel_launch(void* const* d_in, const int* in_sizes, int n_in,
                              void* d_out, int out_size) {
    const float* x     = (const float*)d_in[0];   // [512,256,64]
    const float* Wih0  = (const float*)d_in[1];   // [512,64]
    const float* Wrest = (const float*)d_in[2];   // [4,512,128]
    const float* Whh   = (const float*)d_in[3];   // [5,512,128]
    const float* bih   = (const float*)d_in[4];   // [5,512]
    const float* bhh   = (const float*)d_in[5];   // [5,512]
    float* out = (float*)d_out;                   // [512,256,128]

    float *bufA = nullptr, *bufB = nullptr;
    cudaGetSymbolAddress((void**)&bufA, g_bufA);
    cudaGetSymbolAddress((void**)&bufB, g_bufB);

    const dim3 grid(128), block(256);

    // layer 0: x -> bufA
    lstm_layer_persist<IN_D><<<grid, block>>>(
        x, bufA, Wih0, Whh + 0 * G4 * H_D, bih + 0 * G4, bhh + 0 * G4);
    // layer 1: bufA -> bufB
    lstm_layer_persist<H_D><<<grid, block>>>(
        bufA, bufB, Wrest + 0 * G4 * H_D, Whh + 1 * G4 * H_D,
        bih + 1 * G4, bhh + 1 * G4);
    // layer 2: bufB -> bufA
    lstm_layer_persist<H_D><<<grid, block>>>(
        bufB, bufA, Wrest + 1 * G4 * H_D, Whh + 2 * G4 * H_D,
        bih + 2 * G4, bhh + 2 * G4);
    // layer 3: bufA -> bufB
    lstm_layer_persist<H_D><<<grid, block>>>(
        bufA, bufB, Wrest + 2 * G4 * H_D, Whh + 3 * G4 * H_D,
        bih + 3 * G4, bhh + 3 * G4);
    // layer 4: bufB -> d_out
    lstm_layer_persist<H_D><<<grid, block>>>(
        bufB, out, Wrest + 3 * G4 * H_D, Whh + 4 * G4 * H_D,
        bih + 4 * G4, bhh + 4 * G4);
}

// round 2
// speedup vs baseline: 1.0420x; 1.0420x over previous
#include <cuda_runtime.h>
#include <cstdint>

// ---------------- problem constants ----------------
#define T_SEQ 512
#define B_SZ  256
#define IN_D  64
#define H_D   128
#define G4    512   // 4*H
#define L_N   5

// ping-pong inter-layer activation buffers (scratch via __device__ globals)
__device__ float g_bufA[T_SEQ * B_SZ * H_D];
__device__ float g_bufB[T_SEQ * B_SZ * H_D];

// ---------------- f32x2 packed FMA helpers ----------------
__device__ __forceinline__ void fma2(unsigned long long &acc,
                                     unsigned long long a,
                                     unsigned long long b) {
    asm("fma.rn.f32x2 %0, %1, %2, %3;" : "=l"(acc) : "l"(a), "l"(b), "l"(acc));
}
__device__ __forceinline__ unsigned long long pack2(float lo, float hi) {
    unsigned long long r;
    asm("mov.b64 %0, {%1, %2};" : "=l"(r) : "f"(lo), "f"(hi));
    return r;
}
__device__ __forceinline__ float2 unpack2(unsigned long long v) {
    float2 f;
    asm("mov.b64 {%0, %1}, %2;" : "=f"(f.x), "=f"(f.y) : "l"(v));
    return f;
}
// fast activations (rel err ~1e-6; tolerance is 1e-3 and we sit at 3e-7)
__device__ __forceinline__ float fsig(float x) {
    return __fdividef(1.0f, 1.0f + __expf(-x));
}
__device__ __forceinline__ float ftanh(float x) {
    return __fdividef(2.0f, 1.0f + __expf(-2.0f * x)) - 1.0f;
}

// 4-row dot-product slab: dst[b] (b=0..3) += / = dot over NV*4 floats of
// xh rows (stride KSTRIDE) against this thread's packed weight regs.
// All 32 lanes load the SAME smem address -> broadcast LDS (conflict-free).
template<int NV, int KSTRIDE, bool ACC>
__device__ __forceinline__ void dot4(float* dst, const float* x0,
                                     const unsigned long long* W2) {
    unsigned long long a0 = 0, a1 = 0, a2 = 0, a3 = 0;
#pragma unroll
    for (int kk = 0; kk < NV; kk++) {
        ulonglong2 v0 = *(const ulonglong2*)(x0 + 0 * KSTRIDE + 4 * kk);
        ulonglong2 v1 = *(const ulonglong2*)(x0 + 1 * KSTRIDE + 4 * kk);
        ulonglong2 v2 = *(const ulonglong2*)(x0 + 2 * KSTRIDE + 4 * kk);
        ulonglong2 v3 = *(const ulonglong2*)(x0 + 3 * KSTRIDE + 4 * kk);
        fma2(a0, v0.x, W2[2 * kk]);
        fma2(a1, v1.x, W2[2 * kk]);
        fma2(a2, v2.x, W2[2 * kk]);
        fma2(a3, v3.x, W2[2 * kk]);
        fma2(a0, v0.y, W2[2 * kk + 1]);
        fma2(a1, v1.y, W2[2 * kk + 1]);
        fma2(a2, v2.y, W2[2 * kk + 1]);
        fma2(a3, v3.y, W2[2 * kk + 1]);
    }
    float2 s;
    s = unpack2(a0); dst[0] = (ACC ? dst[0] : 0.0f) + s.x + s.y;
    s = unpack2(a1); dst[1] = (ACC ? dst[1] : 0.0f) + s.x + s.y;
    s = unpack2(a2); dst[2] = (ACC ? dst[2] : 0.0f) + s.x + s.y;
    s = unpack2(a3); dst[3] = (ACC ? dst[3] : 0.0f) + s.x + s.y;
}

// ============================================================================
// Persistent LSTM layer. Grid 128 CTAs, cluster of 4. Cluster c owns batch
// rows [8c, 8c+8); CTA rank r owns hidden slice j in [32r, 32r+32) of all 4
// gates (128 gate rows). 512 threads: warp w -> K-quarter kq=w&3, gate row
// rr = (w>>2)*32+lane. Weights (1/4 of K per gate row) live in registers.
//
// Per step:   B-phase: h-part dots (needs h[t-1])
//             combine + activations + publish h (own smem + 3 peers DSMEM)
//             barrier.cluster.arrive          (releases DSMEM h stores)
//             A-phase: x-part dots for t+1    <-- hides barrier latency
//             barrier.cluster.wait
// ============================================================================
template<int KIN>
__global__ void __launch_bounds__(512, 1) __cluster_dims__(4, 1, 1)
lstm_layer_persist(const float* __restrict__ in,   // [T, B, KIN]
                   float* __restrict__ out,        // [T, B, H]
                   const float* __restrict__ Wih,  // [4H, KIN]
                   const float* __restrict__ Whh,  // [4H, H]
                   const float* __restrict__ bih,  // [4H]
                   const float* __restrict__ bhh)  // [4H]
{
    constexpr int K   = KIN + H_D;     // 192 or 256
    constexpr int KQX = KIN / 4;       // x floats per thread quarter (16/32)
    constexpr int NVX = KQX / 4;       // 16B chunks in x quarter (4/8)
    constexpr int NVH = 8;             // 32 h floats per quarter / 4

    __align__(16) __shared__ float xh[2][8][K];     // [x | h], double buffered
    __shared__ float gbuf[4][8][128];               // partial sums per quarter

    const int tid  = threadIdx.x;
    const int lane = tid & 31;
    const int w    = tid >> 5;
    const int kq   = w & 3;                    // K quarter
    const int rr   = ((w >> 2) << 5) + lane;   // local gate row 0..127

    uint32_t rank;
    asm("mov.u32 %0, %%cluster_ctarank;" : "=r"(rank));
    const int b0 = (blockIdx.x >> 2) * 8;

    const int gq = rr >> 5;
    const int gr = gq * H_D + (int)rank * 32 + (rr & 31);  // global gate row

    // ---- weights into registers (f32x2 packed) ----
    unsigned long long Wx2[KQX / 2];
    unsigned long long Wh2[16];
#pragma unroll
    for (int i = 0; i < KQX / 2; i++) {
        const int col = kq * KQX + 2 * i;
        Wx2[i] = pack2(Wih[gr * KIN + col], Wih[gr * KIN + col + 1]);
    }
#pragma unroll
    for (int i = 0; i < 16; i++) {
        const int col = kq * 32 + 2 * i;
        Wh2[i] = pack2(Whh[gr * H_D + col], Whh[gr * H_D + col + 1]);
    }

    // ---- output identity (threads < 256) ----
    const int ob    = tid >> 5;                // batch row 0..7 (valid tid<256)
    const int oj    = tid & 31;
    const int jglob = (int)rank * 32 + oj;
    float bsum[4];
#pragma unroll
    for (int g = 0; g < 4; g++)
        bsum[g] = bih[g * H_D + jglob] + bhh[g * H_D + jglob];
    float c_state = 0.0f;

    // ---- x prefetch identity ----
    const int prow = tid >> 6;                        // 0..7
    const int pcol = (KIN == 128) ? ((tid & 63) << 1) : (tid & 63);
    const float* pf_src = in + ((size_t)b0 + prow) * KIN + pcol;  // t = 0
    float* out_p = out + ((size_t)b0 + ob) * H_D + jglob;         // t = 0

    // ---- prologue: stage x(0), zero h(−1), A-phase for t=0 ----
    if (KIN == 128) *(float2*)(&xh[0][prow][pcol]) = *(const float2*)pf_src;
    else            xh[0][prow][pcol] = *pf_src;
    for (int idx = tid; idx < 8 * H_D; idx += 512)
        xh[0][idx >> 7][KIN + (idx & 127)] = 0.0f;
    __syncthreads();

    float accAf[8];
    dot4<NVX, K, false>(accAf + 0, &xh[0][0][kq * KQX], Wx2);
    dot4<NVX, K, false>(accAf + 4, &xh[0][4][kq * KQX], Wx2);

    for (int t = 0; t < T_SEQ; t++) {
        const int cur  = t & 1;
        const int nxt  = cur ^ 1;
        const bool more = (t + 1 < T_SEQ);

        // early LDG of x(t+1) (consumed at staging, latency hidden)
        float2 pf = make_float2(0.0f, 0.0f);
        if (more) {
            const float* s = pf_src + (size_t)B_SZ * KIN;
            if (KIN == 128) pf = *(const float2*)s;
            else            pf.x = *s;
            pf_src = s;
        }

        // ---- B-phase: h-part dots, fold into accAf, publish partials ----
        dot4<NVH, K, true>(accAf + 0, &xh[cur][0][KIN + kq * 32], Wh2);
        dot4<NVH, K, true>(accAf + 4, &xh[cur][4][KIN + kq * 32], Wh2);
#pragma unroll
        for (int b = 0; b < 8; b++) gbuf[kq][b][rr] = accAf[b];
        __syncthreads();

        // ---- combine quarters, activations, state update, publish h ----
        if (tid < 256) {
            float gv[4];
#pragma unroll
            for (int g = 0; g < 4; g++)
                gv[g] = bsum[g] + gbuf[0][ob][g * 32 + oj]
                               + gbuf[1][ob][g * 32 + oj]
                               + gbuf[2][ob][g * 32 + oj]
                               + gbuf[3][ob][g * 32 + oj];
            const float ig = fsig(gv[0]);
            const float fg = fsig(gv[1]);
            const float gg = ftanh(gv[2]);
            const float og = fsig(gv[3]);
            c_state = fg * c_state + ig * gg;
            const float h = og * ftanh(c_state);

            if (more) {
                xh[nxt][ob][KIN + jglob] = h;
                const uint32_t laddr =
                    (uint32_t)__cvta_generic_to_shared(&xh[nxt][ob][KIN + jglob]);
#pragma unroll
                for (int pr = 0; pr < 4; pr++) {
                    if (pr != (int)rank) {
                        asm volatile(
                            "{ .reg .b32 ra;\n\t"
                            "  mapa.shared::cluster.u32 ra, %0, %1;\n\t"
                            "  st.shared::cluster.f32 [ra], %2; }"
                            :: "r"(laddr), "r"(pr), "f"(h) : "memory");
                    }
                }
            }
            *out_p = h;                                   // coalesced STG
            out_p += (size_t)B_SZ * H_D;
        }

        // ---- stage x(t+1) into next buffer ----
        if (more) {
            if (KIN == 128) *(float2*)(&xh[nxt][prow][pcol]) = pf;
            else            xh[nxt][prow][pcol] = pf.x;
        }
        __syncthreads();

        // ---- hide cluster barrier behind A-phase of t+1 ----
        if (more) {
            asm volatile("barrier.cluster.arrive.aligned;" ::: "memory");
            dot4<NVX, K, false>(accAf + 0, &xh[nxt][0][kq * KQX], Wx2);
            dot4<NVX, K, false>(accAf + 4, &xh[nxt][4][kq * KQX], Wx2);
            asm volatile("barrier.cluster.wait.aligned;"   ::: "memory");
        }
    }
}

// ============================================================================
// kernel_launch: 5 sequential layer kernels (graph-capturable, no allocs)
// ============================================================================
extern "C" void kernel_launch(void* const* d_in, const int* in_sizes, int n_in,
                              void* d_out, int out_size) {
    const float* x     = (const float*)d_in[0];   // [512,256,64]
    const float* Wih0  = (const float*)d_in[1];   // [512,64]
    const float* Wrest = (const float*)d_in[2];   // [4,512,128]
    const float* Whh   = (const float*)d_in[3];   // [5,512,128]
    const float* bih   = (const float*)d_in[4];   // [5,512]
    const float* bhh   = (const float*)d_in[5];   // [5,512]
    float* out = (float*)d_out;                   // [512,256,128]

    float *bufA = nullptr, *bufB = nullptr;
    cudaGetSymbolAddress((void**)&bufA, g_bufA);
    cudaGetSymbolAddress((void**)&bufB, g_bufB);

    const dim3 grid(128), block(512);

    lstm_layer_persist<IN_D><<<grid, block>>>(
        x, bufA, Wih0, Whh + 0 * G4 * H_D, bih + 0 * G4, bhh + 0 * G4);
    lstm_layer_persist<H_D><<<grid, block>>>(
        bufA, bufB, Wrest + 0 * G4 * H_D, Whh + 1 * G4 * H_D,
        bih + 1 * G4, bhh + 1 * G4);
    lstm_layer_persist<H_D><<<grid, block>>>(
        bufB, bufA, Wrest + 1 * G4 * H_D, Whh + 2 * G4 * H_D,
        bih + 2 * G4, bhh + 2 * G4);
    lstm_layer_persist<H_D><<<grid, block>>>(
        bufA, bufB, Wrest + 2 * G4 * H_D, Whh + 3 * G4 * H_D,
        bih + 3 * G4, bhh + 3 * G4);
    lstm_layer_persist<H_D><<<grid, block>>>(
        bufB, out, Wrest + 3 * G4 * H_D, Whh + 4 * G4 * H_D,
        bih + 4 * G4, bhh + 4 * G4);
}

// round 3
// speedup vs baseline: 1.2419x; 1.1918x over previous
#include <cuda_runtime.h>
#include <cstdint>

// ---------------- problem constants ----------------
#define T_SEQ 512
#define B_SZ  256
#define IN_D  64
#define H_D   128
#define G4    512   // 4*H
#define L_N   5

// ping-pong inter-layer activation buffers (scratch via __device__ globals)
__device__ float g_bufA[T_SEQ * B_SZ * H_D];
__device__ float g_bufB[T_SEQ * B_SZ * H_D];

// ---------------- f32x2 packed FMA helpers ----------------
__device__ __forceinline__ void fma2(unsigned long long &acc,
                                     unsigned long long a,
                                     unsigned long long b) {
    asm("fma.rn.f32x2 %0, %1, %2, %3;" : "=l"(acc) : "l"(a), "l"(b), "l"(acc));
}
__device__ __forceinline__ unsigned long long pack2(float lo, float hi) {
    unsigned long long r;
    asm("mov.b64 %0, {%1, %2};" : "=l"(r) : "f"(lo), "f"(hi));
    return r;
}
__device__ __forceinline__ float sum2(unsigned long long v) {
    float lo, hi;
    asm("mov.b64 {%0, %1}, %2;" : "=f"(lo), "=f"(hi) : "l"(v));
    return lo + hi;
}
__device__ __forceinline__ float fsig(float x) {
    return __fdividef(1.0f, 1.0f + __expf(-x));
}
__device__ __forceinline__ float ftanh(float x) {
    return __fdividef(2.0f, 1.0f + __expf(-2.0f * x)) - 1.0f;
}

// One dot pass: 4 batch rows x 2 gate rows x (4*NV) k-values.
// p points at this thread's k-slice of batch row 0; row stride RS floats.
// Each LDS.128 (broadcast, conflict-free) feeds 4 fma2 (2 rows x 2 pairs).
template<int NV, int RS>
__device__ __forceinline__ void dot_pass(unsigned long long* a0,
                                         unsigned long long* a1,
                                         const float* __restrict__ p,
                                         const unsigned long long* W0,
                                         const unsigned long long* W1) {
#pragma unroll
    for (int kk = 0; kk < NV; kk++) {
#pragma unroll
        for (int b = 0; b < 4; b++) {
            ulonglong2 v = *(const ulonglong2*)(p + b * RS + 4 * kk);
            fma2(a0[b], v.x, W0[2 * kk]);
            fma2(a0[b], v.y, W0[2 * kk + 1]);
            fma2(a1[b], v.x, W1[2 * kk]);
            fma2(a1[b], v.y, W1[2 * kk + 1]);
        }
    }
}

// ============================================================================
// Persistent LSTM layer. Grid 128 CTAs, cluster of 4; cluster owns 8 batch
// rows, CTA rank r owns hidden slice [32r, 32r+32) of all 4 gates (128 gate
// rows). 512 threads = 16 warps:
//   warps 0-7  (x-group): K-slices of the input part, slice len KIN/4.
//                         At iter t they compute x-dots for step t+1
//                         (independent of h -> runs under the cluster barrier)
//   warps 8-15 (h-group): K-slices (32) of the recurrent part, h-dots for t.
// Each thread covers 2 gate rows (r0 = rg*64+lane, r1 = r0+32) sharing one
// k-slice -> every broadcast LDS.128 feeds 4 fma2.
// Partials land in gbuf[parity][8 slices][8 b][128 rows]; 256 epilogue
// threads combine, apply activations, update c, publish h to own smem +
// 3 peer CTAs (DSMEM), and write the layer output.
// ============================================================================
template<int KIN>
__global__ void __launch_bounds__(512, 1) __cluster_dims__(4, 1, 1)
lstm_layer(const float* __restrict__ in,   // [T, B, KIN]
           float* __restrict__ out,        // [T, B, H]
           const float* __restrict__ Wih,  // [4H, KIN]
           const float* __restrict__ Whh,  // [4H, H]
           const float* __restrict__ bih,  // [4H]
           const float* __restrict__ bhh)  // [4H]
{
    constexpr int XSL = KIN / 4;       // x slice length (16 or 32)
    constexpr int NVX = XSL / 4;       // 16B chunks per x slice (4 or 8)

    extern __shared__ float sm[];
    float* gbuf = sm;                                  // [2][8][8][128]
    float* xs   = sm + 2 * 8 * 8 * 128;                // [2][8][KIN]
    float* hs   = xs + 2 * 8 * KIN;                    // [2][8][128]

    const int tid  = threadIdx.x;
    const int lane = tid & 31;
    const int w    = tid >> 5;
    const bool isx = (w < 8);
    const int rg   = w & 1;
    const int r0   = rg * 64 + lane;     // local gate rows r0, r0+32
    const int r1   = r0 + 32;

    uint32_t rank;
    asm("mov.u32 %0, %%cluster_ctarank;" : "=r"(rank));
    const int b0 = (blockIdx.x >> 2) * 8;

    const int k0 = isx ? (w >> 1) * XSL : ((w - 8) >> 1) * 32;
    const int sl = isx ? (w >> 1)       : 4 + ((w - 8) >> 1);

    const int gr0 = (r0 >> 5) * H_D + (int)rank * 32 + (r0 & 31);
    const int gr1 = (r1 >> 5) * H_D + (int)rank * 32 + (r1 & 31);

    // ---- weights into registers: 2 rows x (k-slice) packed (k,k+1) ----
    unsigned long long W0[16], W1[16];
    if (isx) {
#pragma unroll
        for (int i = 0; i < XSL / 2; i++) {
            const int c = k0 + 2 * i;
            W0[i] = pack2(Wih[gr0 * KIN + c], Wih[gr0 * KIN + c + 1]);
            W1[i] = pack2(Wih[gr1 * KIN + c], Wih[gr1 * KIN + c + 1]);
        }
    } else {
#pragma unroll
        for (int i = 0; i < 16; i++) {
            const int c = k0 + 2 * i;
            W0[i] = pack2(Whh[gr0 * H_D + c], Whh[gr0 * H_D + c + 1]);
            W1[i] = pack2(Whh[gr1 * H_D + c], Whh[gr1 * H_D + c + 1]);
        }
    }

    // ---- epilogue identity (threads < 256) ----
    const int ob    = tid >> 5;                 // batch row 0..7
    const int oj    = tid & 31;
    const int jglob = (int)rank * 32 + oj;
    float bsum[4];
#pragma unroll
    for (int g = 0; g < 4; g++)
        bsum[g] = bih[g * H_D + jglob] + bhh[g * H_D + jglob];
    float c_state = 0.0f;
    float* out_p = out + ((size_t)b0 + ob) * H_D + jglob;

    // ---- staging identity: x(t+2) loaded/stored as float2 per thread ----
    const bool stager = (tid < 4 * KIN);        // 8*KIN/2 float2 slots
    const int  srow   = (2 * tid) / KIN;
    const int  scol   = (2 * tid) % KIN;
    const float* st_src =
        in + ((size_t)2 * B_SZ + b0 + srow) * KIN + scol;   // x(2)

    // ---- prologue: stage x(0), x(1); zero h(-1); x-dots for step 0 ----
    for (int i = tid; i < 8 * KIN; i += 512) {
        const int r = i / KIN, c = i % KIN;
        xs[0 * 8 * KIN + i] = in[((size_t)0 * B_SZ + b0 + r) * KIN + c];
        xs[1 * 8 * KIN + i] = in[((size_t)1 * B_SZ + b0 + r) * KIN + c];
    }
    for (int i = tid; i < 8 * H_D; i += 512) hs[i] = 0.0f;
    __syncthreads();

    if (isx) {
        unsigned long long a0[4] = {0, 0, 0, 0}, a1[4] = {0, 0, 0, 0};
        dot_pass<NVX, KIN>(a0, a1, xs + k0, W0, W1);
        float* g0 = gbuf + (size_t)sl * 8 * 128;
#pragma unroll
        for (int b = 0; b < 4; b++) {
            g0[b * 128 + r0] = sum2(a0[b]);
            g0[b * 128 + r1] = sum2(a1[b]);
        }
#pragma unroll
        for (int b = 0; b < 4; b++) a0[b] = a1[b] = 0ull;
        dot_pass<NVX, KIN>(a0, a1, xs + 4 * KIN + k0, W0, W1);
#pragma unroll
        for (int b = 0; b < 4; b++) {
            g0[(b + 4) * 128 + r0] = sum2(a0[b]);
            g0[(b + 4) * 128 + r1] = sum2(a1[b]);
        }
    }
    asm volatile("barrier.cluster.arrive.aligned;" ::: "memory");

    for (int t = 0; t < T_SEQ; t++) {
        const int cur = t & 1;
        const int nxt = cur ^ 1;

        // h(t-1) from all 4 ranks is published once the barrier releases
        asm volatile("barrier.cluster.wait.aligned;" ::: "memory");

        // early LDG of x(t+2) (consumed by STS below; latency hidden)
        float2 pf;
        const bool do_stage = stager && (t + 2 < T_SEQ);
        if (do_stage) pf = *(const float2*)st_src;

        if (isx) {
            // x-dots for step t+1 (off the serial chain)
            if (t + 1 < T_SEQ) {
                const float* base = xs + nxt * 8 * KIN + k0;
                float* g0 = gbuf + ((size_t)nxt * 8 + sl) * 8 * 128;
                unsigned long long a0[4] = {0, 0, 0, 0}, a1[4] = {0, 0, 0, 0};
                dot_pass<NVX, KIN>(a0, a1, base, W0, W1);
#pragma unroll
                for (int b = 0; b < 4; b++) {
                    g0[b * 128 + r0] = sum2(a0[b]);
                    g0[b * 128 + r1] = sum2(a1[b]);
                }
#pragma unroll
                for (int b = 0; b < 4; b++) a0[b] = a1[b] = 0ull;
                dot_pass<NVX, KIN>(a0, a1, base + 4 * KIN, W0, W1);
#pragma unroll
                for (int b = 0; b < 4; b++) {
                    g0[(b + 4) * 128 + r0] = sum2(a0[b]);
                    g0[(b + 4) * 128 + r1] = sum2(a1[b]);
                }
            }
        } else {
            // h-dots for step t (the serial chain)
            const float* base = hs + cur * 8 * H_D + k0;
            float* g0 = gbuf + ((size_t)cur * 8 + sl) * 8 * 128;
            unsigned long long a0[4] = {0, 0, 0, 0}, a1[4] = {0, 0, 0, 0};
            dot_pass<8, H_D>(a0, a1, base, W0, W1);
#pragma unroll
            for (int b = 0; b < 4; b++) {
                g0[b * 128 + r0] = sum2(a0[b]);
                g0[b * 128 + r1] = sum2(a1[b]);
            }
#pragma unroll
            for (int b = 0; b < 4; b++) a0[b] = a1[b] = 0ull;
            dot_pass<8, H_D>(a0, a1, base + 4 * H_D, W0, W1);
#pragma unroll
            for (int b = 0; b < 4; b++) {
                g0[(b + 4) * 128 + r0] = sum2(a0[b]);
                g0[(b + 4) * 128 + r1] = sum2(a1[b]);
            }
        }

        // stage x(t+2) into xs[t&1] (read next iter, after the sync below)
        if (do_stage) {
            *(float2*)(xs + cur * 8 * KIN + srow * KIN + scol) = pf;
            st_src += (size_t)B_SZ * KIN;
        }

        __syncthreads();   // gbuf[cur] complete (x from iter t-1, h from t)

        if (tid < 256) {
            const float* gb = gbuf + (size_t)cur * 8 * 8 * 128;
            float gv[4];
#pragma unroll
            for (int g = 0; g < 4; g++) {
                float s = bsum[g];
#pragma unroll
                for (int q = 0; q < 8; q++)
                    s += gb[(q * 8 + ob) * 128 + g * 32 + oj];
                gv[g] = s;
            }
            const float ig = fsig(gv[0]);
            const float fg = fsig(gv[1]);
            const float gg = ftanh(gv[2]);
            const float og = fsig(gv[3]);
            c_state = fg * c_state + ig * gg;
            const float h = og * ftanh(c_state);

            if (t + 1 < T_SEQ) {
                float* hp = hs + nxt * 8 * H_D + ob * H_D + jglob;
                *hp = h;
                const uint32_t laddr = (uint32_t)__cvta_generic_to_shared(hp);
#pragma unroll
                for (int pr = 0; pr < 4; pr++) {
                    if (pr != (int)rank) {
                        asm volatile(
                            "{ .reg .b32 ra;\n\t"
                            "  mapa.shared::cluster.u32 ra, %0, %1;\n\t"
                            "  st.shared::cluster.f32 [ra], %2; }"
                            :: "r"(laddr), "r"(pr), "f"(h) : "memory");
                    }
                }
            }
            *out_p = h;
            out_p += (size_t)B_SZ * H_D;
        }

        if (t + 1 < T_SEQ)
            asm volatile("barrier.cluster.arrive.aligned;" ::: "memory");
    }
}

// ============================================================================
// kernel_launch: 5 sequential layer kernels (graph-capturable, no allocs)
// ============================================================================
static const int SMEM64  = (2 * 8 * 8 * 128 + 2 * 8 * 64  + 2 * 8 * 128) * 4;
static const int SMEM128 = (2 * 8 * 8 * 128 + 2 * 8 * 128 + 2 * 8 * 128) * 4;

extern "C" void kernel_launch(void* const* d_in, const int* in_sizes, int n_in,
                              void* d_out, int out_size) {
    const float* x     = (const float*)d_in[0];   // [512,256,64]
    const float* Wih0  = (const float*)d_in[1];   // [512,64]
    const float* Wrest = (const float*)d_in[2];   // [4,512,128]
    const float* Whh   = (const float*)d_in[3];   // [5,512,128]
    const float* bih   = (const float*)d_in[4];   // [5,512]
    const float* bhh   = (const float*)d_in[5];   // [5,512]
    float* out = (float*)d_out;                   // [512,256,128]

    float *bufA = nullptr, *bufB = nullptr;
    cudaGetSymbolAddress((void**)&bufA, g_bufA);
    cudaGetSymbolAddress((void**)&bufB, g_bufB);

    cudaFuncSetAttribute(lstm_layer<IN_D>,
        cudaFuncAttributeMaxDynamicSharedMemorySize, SMEM64);
    cudaFuncSetAttribute(lstm_layer<H_D>,
        cudaFuncAttributeMaxDynamicSharedMemorySize, SMEM128);

    const dim3 grid(128), block(512);

    lstm_layer<IN_D><<<grid, block, SMEM64>>>(
        x, bufA, Wih0, Whh + 0 * G4 * H_D, bih + 0 * G4, bhh + 0 * G4);
    lstm_layer<H_D><<<grid, block, SMEM128>>>(
        bufA, bufB, Wrest + 0 * G4 * H_D, Whh + 1 * G4 * H_D,
        bih + 1 * G4, bhh + 1 * G4);
    lstm_layer<H_D><<<grid, block, SMEM128>>>(
        bufB, bufA, Wrest + 1 * G4 * H_D, Whh + 2 * G4 * H_D,
        bih + 2 * G4, bhh + 2 * G4);
    lstm_layer<H_D><<<grid, block, SMEM128>>>(
        bufA, bufB, Wrest + 2 * G4 * H_D, Whh + 3 * G4 * H_D,
        bih + 3 * G4, bhh + 3 * G4);
    lstm_layer<H_D><<<grid, block, SMEM128>>>(
        bufB, out, Wrest + 3 * G4 * H_D, Whh + 4 * G4 * H_D,
        bih + 4 * G4, bhh + 4 * G4);
}

// round 4
// speedup vs baseline: 1.2583x; 1.0131x over previous
#include <cuda_runtime.h>
#include <cstdint>

// ---------------- problem constants ----------------
#define T_SEQ 512
#define B_SZ  256
#define IN_D  64
#define H_D   128
#define G4    512   // 4*H
#define L_N   5

// ping-pong inter-layer activation buffers (scratch via __device__ globals)
__device__ float g_bufA[T_SEQ * B_SZ * H_D];
__device__ float g_bufB[T_SEQ * B_SZ * H_D];

// ---------------- f32x2 packed FMA helpers ----------------
__device__ __forceinline__ void fma2(unsigned long long &acc,
                                     unsigned long long a,
                                     unsigned long long b) {
    asm("fma.rn.f32x2 %0, %1, %2, %3;" : "=l"(acc) : "l"(a), "l"(b), "l"(acc));
}
__device__ __forceinline__ unsigned long long pack2(float lo, float hi) {
    unsigned long long r;
    asm("mov.b64 %0, {%1, %2};" : "=l"(r) : "f"(lo), "f"(hi));
    return r;
}
__device__ __forceinline__ float sum2(unsigned long long v) {
    float lo, hi;
    asm("mov.b64 {%0, %1}, %2;" : "=f"(lo), "=f"(hi) : "l"(v));
    return lo + hi;
}
__device__ __forceinline__ float fsig(float x) {
    return __fdividef(1.0f, 1.0f + __expf(-x));
}
__device__ __forceinline__ float ftanh(float x) {
    return __fdividef(2.0f, 1.0f + __expf(-2.0f * x)) - 1.0f;
}

// One dot pass: 4 batch rows x 2 gate rows x (4*NV) k-values.
// p points at this thread's k-slice of batch row 0; row stride RS floats.
// Each LDS.128 (broadcast, conflict-free) feeds 4 fma2 (2 rows x 2 pairs).
template<int NV, int RS>
__device__ __forceinline__ void dot_pass(unsigned long long* a0,
                                         unsigned long long* a1,
                                         const float* __restrict__ p,
                                         const unsigned long long* W0,
                                         const unsigned long long* W1) {
#pragma unroll
    for (int kk = 0; kk < NV; kk++) {
#pragma unroll
        for (int b = 0; b < 4; b++) {
            ulonglong2 v = *(const ulonglong2*)(p + b * RS + 4 * kk);
            fma2(a0[b], v.x, W0[2 * kk]);
            fma2(a0[b], v.y, W0[2 * kk + 1]);
            fma2(a1[b], v.x, W1[2 * kk]);
            fma2(a1[b], v.y, W1[2 * kk + 1]);
        }
    }
}

// Full slab: 8 batch rows, write partials for 2 gate rows into g0.
template<int NV, int RS>
__device__ __forceinline__ void slab(float* __restrict__ g0,
                                     const float* __restrict__ base,
                                     const unsigned long long* W0,
                                     const unsigned long long* W1,
                                     int r0, int r1) {
    unsigned long long a0[4] = {0, 0, 0, 0}, a1[4] = {0, 0, 0, 0};
    dot_pass<NV, RS>(a0, a1, base, W0, W1);
#pragma unroll
    for (int b = 0; b < 4; b++) {
        g0[b * 128 + r0] = sum2(a0[b]);
        g0[b * 128 + r1] = sum2(a1[b]);
    }
#pragma unroll
    for (int b = 0; b < 4; b++) a0[b] = a1[b] = 0ull;
    dot_pass<NV, RS>(a0, a1, base + 4 * RS, W0, W1);
#pragma unroll
    for (int b = 0; b < 4; b++) {
        g0[(b + 4) * 128 + r0] = sum2(a0[b]);
        g0[(b + 4) * 128 + r1] = sum2(a1[b]);
    }
}

// ============================================================================
// Persistent LSTM layer. Grid 128 CTAs, cluster of 4; cluster owns 8 batch
// rows, CTA rank r owns hidden slice [32r, 32r+32) of all 4 gates.
// 512 threads = 16 warps:
//   warps 0-7  (x-group): x-part dots for step t+1, issued BEFORE the cluster
//                         wait -> they bridge the arrive->wait gap and hide
//                         the barrier latency. Then they run the epilogue.
//   warps 8-15 (h-group): LDG-prefetch x(t+2) before the wait; h-part dots
//                         for step t after it; then stage x(t+2) to smem.
// Each thread covers 2 gate rows sharing one k-slice -> every broadcast
// LDS.128 feeds 4 fma2.
// ============================================================================
template<int KIN>
__global__ void __launch_bounds__(512, 1) __cluster_dims__(4, 1, 1)
lstm_layer(const float* __restrict__ in,   // [T, B, KIN]
           float* __restrict__ out,        // [T, B, H]
           const float* __restrict__ Wih,  // [4H, KIN]
           const float* __restrict__ Whh,  // [4H, H]
           const float* __restrict__ bih,  // [4H]
           const float* __restrict__ bhh)  // [4H]
{
    constexpr int XSL = KIN / 4;       // x slice length (16 or 32)
    constexpr int NVX = XSL / 4;       // 16B chunks per x slice (4 or 8)

    extern __shared__ float sm[];
    float* gbuf = sm;                                  // [2][8][8][128]
    float* xs   = sm + 2 * 8 * 8 * 128;                // [2][8][KIN]
    float* hs   = xs + 2 * 8 * KIN;                    // [2][8][128]

    const int tid  = threadIdx.x;
    const int lane = tid & 31;
    const int w    = tid >> 5;
    const bool isx = (w < 8);
    const int rg   = w & 1;
    const int r0   = rg * 64 + lane;     // local gate rows r0, r0+32
    const int r1   = r0 + 32;

    uint32_t rank;
    asm("mov.u32 %0, %%cluster_ctarank;" : "=r"(rank));
    const int b0 = (blockIdx.x >> 2) * 8;

    const int k0 = isx ? (w >> 1) * XSL : ((w - 8) >> 1) * 32;
    const int sl = isx ? (w >> 1)       : 4 + ((w - 8) >> 1);

    const int gr0 = (r0 >> 5) * H_D + (int)rank * 32 + (r0 & 31);
    const int gr1 = (r1 >> 5) * H_D + (int)rank * 32 + (r1 & 31);

    // ---- weights into registers: 2 rows x (k-slice) packed (k,k+1) ----
    unsigned long long W0[16], W1[16];
    if (isx) {
#pragma unroll
        for (int i = 0; i < XSL / 2; i++) {
            const int c = k0 + 2 * i;
            W0[i] = pack2(Wih[gr0 * KIN + c], Wih[gr0 * KIN + c + 1]);
            W1[i] = pack2(Wih[gr1 * KIN + c], Wih[gr1 * KIN + c + 1]);
        }
    } else {
#pragma unroll
        for (int i = 0; i < 16; i++) {
            const int c = k0 + 2 * i;
            W0[i] = pack2(Whh[gr0 * H_D + c], Whh[gr0 * H_D + c + 1]);
            W1[i] = pack2(Whh[gr1 * H_D + c], Whh[gr1 * H_D + c + 1]);
        }
    }

    // ---- epilogue identity (threads < 256 = x-warps) ----
    const int ob    = tid >> 5;                 // batch row 0..7
    const int oj    = tid & 31;
    const int jglob = (int)rank * 32 + oj;
    float bsum[4];
#pragma unroll
    for (int g = 0; g < 4; g++)
        bsum[g] = bih[g * H_D + jglob] + bhh[g * H_D + jglob];
    float c_state = 0.0f;
    float* out_p = out + ((size_t)b0 + ob) * H_D + jglob;

    // ---- staging identity (h-warps, tid >= 256): x(t+2) per thread ----
    // KIN=128: float4 each; KIN=64: float2 each. 256 threads cover 8*KIN.
    const int  si   = tid & 255;
    const int  srow = si >> 5;
    const int  scol = (KIN == 128) ? ((si & 31) << 2) : ((si & 31) << 1);
    const float* st_src =
        in + ((size_t)2 * B_SZ + b0 + srow) * KIN + scol;   // x(2)

    // ---- prologue: stage x(0), x(1); zero h(-1); x-dots for step 0 ----
    for (int i = tid; i < 8 * KIN; i += 512) {
        const int r = i / KIN, c = i % KIN;
        xs[0 * 8 * KIN + i] = in[((size_t)0 * B_SZ + b0 + r) * KIN + c];
        xs[1 * 8 * KIN + i] = in[((size_t)1 * B_SZ + b0 + r) * KIN + c];
    }
    for (int i = tid; i < 8 * H_D; i += 512) hs[i] = 0.0f;
    __syncthreads();

    if (isx)
        slab<NVX, KIN>(gbuf + (size_t)sl * 8 * 128, xs + k0, W0, W1, r0, r1);
    asm volatile("barrier.cluster.arrive.aligned;" ::: "memory");

    for (int t = 0; t < T_SEQ; t++) {
        const int cur = t & 1;
        const int nxt = cur ^ 1;
        const bool do_stage = (!isx) && (t + 2 < T_SEQ);

        // ---- pre-wait work: x-dots for t+1 (x-warps) hide the barrier;
        //      h-warps issue the x(t+2) LDG (DRAM latency hidden too).
        float4 pf;
        if (isx) {
            if (t + 1 < T_SEQ)
                slab<NVX, KIN>(gbuf + ((size_t)nxt * 8 + sl) * 8 * 128,
                               xs + nxt * 8 * KIN + k0, W0, W1, r0, r1);
        } else if (do_stage) {
            if (KIN == 128) pf = *(const float4*)st_src;
            else { const float2 p2 = *(const float2*)st_src;
                   pf.x = p2.x; pf.y = p2.y; }
        }

        // h(t-1) from all 4 ranks is published once the barrier releases
        asm volatile("barrier.cluster.wait.aligned;" ::: "memory");

        if (!isx) {
            // ---- h-dots for step t (the serial chain) ----
            slab<8, H_D>(gbuf + ((size_t)cur * 8 + sl) * 8 * 128,
                         hs + cur * 8 * H_D + k0, W0, W1, r0, r1);
            // stage x(t+2) into xs[cur] (consumed in iter t+1, after sync)
            if (do_stage) {
                float* d = xs + cur * 8 * KIN + srow * KIN + scol;
                if (KIN == 128) *(float4*)d = pf;
                else            *(float2*)d = make_float2(pf.x, pf.y);
                st_src += (size_t)B_SZ * KIN;
            }
        }

        __syncthreads();   // gbuf[cur] complete (x from iter t-1, h from t)

        if (tid < 256) {
            const float* gb = gbuf + (size_t)cur * 8 * 8 * 128;
            float gv[4];
#pragma unroll
            for (int g = 0; g < 4; g++) {
                float s = bsum[g];
#pragma unroll
                for (int q = 0; q < 8; q++)
                    s += gb[(q * 8 + ob) * 128 + g * 32 + oj];
                gv[g] = s;
            }
            const float ig = fsig(gv[0]);
            const float fg = fsig(gv[1]);
            const float gg = ftanh(gv[2]);
            const float og = fsig(gv[3]);
            c_state = fg * c_state + ig * gg;
            const float h = og * ftanh(c_state);

            if (t + 1 < T_SEQ) {
                float* hp = hs + nxt * 8 * H_D + ob * H_D + jglob;
                *hp = h;
                const uint32_t laddr = (uint32_t)__cvta_generic_to_shared(hp);
#pragma unroll
                for (int pr = 0; pr < 4; pr++) {
                    if (pr != (int)rank) {
                        asm volatile(
                            "{ .reg .b32 ra;\n\t"
                            "  mapa.shared::cluster.u32 ra, %0, %1;\n\t"
                            "  st.shared::cluster.f32 [ra], %2; }"
                            :: "r"(laddr), "r"(pr), "f"(h) : "memory");
                    }
                }
            }
            *out_p = h;
            out_p += (size_t)B_SZ * H_D;
        }

        if (t + 1 < T_SEQ)
            asm volatile("barrier.cluster.arrive.aligned;" ::: "memory");
    }
}

// ============================================================================
// kernel_launch: 5 sequential layer kernels (graph-capturable, no allocs)
// ============================================================================
static const int SMEM64  = (2 * 8 * 8 * 128 + 2 * 8 * 64  + 2 * 8 * 128) * 4;
static const int SMEM128 = (2 * 8 * 8 * 128 + 2 * 8 * 128 + 2 * 8 * 128) * 4;

extern "C" void kernel_launch(void* const* d_in, const int* in_sizes, int n_in,
                              void* d_out, int out_size) {
    const float* x     = (const float*)d_in[0];   // [512,256,64]
    const float* Wih0  = (const float*)d_in[1];   // [512,64]
    const float* Wrest = (const float*)d_in[2];   // [4,512,128]
    const float* Whh   = (const float*)d_in[3];   // [5,512,128]
    const float* bih   = (const float*)d_in[4];   // [5,512]
    const float* bhh   = (const float*)d_in[5];   // [5,512]
    float* out = (float*)d_out;                   // [512,256,128]

    float *bufA = nullptr, *bufB = nullptr;
    cudaGetSymbolAddress((void**)&bufA, g_bufA);
    cudaGetSymbolAddress((void**)&bufB, g_bufB);

    cudaFuncSetAttribute(lstm_layer<IN_D>,
        cudaFuncAttributeMaxDynamicSharedMemorySize, SMEM64);
    cudaFuncSetAttribute(lstm_layer<H_D>,
        cudaFuncAttributeMaxDynamicSharedMemorySize, SMEM128);

    const dim3 grid(128), block(512);

    lstm_layer<IN_D><<<grid, block, SMEM64>>>(
        x, bufA, Wih0, Whh + 0 * G4 * H_D, bih + 0 * G4, bhh + 0 * G4);
    lstm_layer<H_D><<<grid, block, SMEM128>>>(
        bufA, bufB, Wrest + 0 * G4 * H_D, Whh + 1 * G4 * H_D,
        bih + 1 * G4, bhh + 1 * G4);
    lstm_layer<H_D><<<grid, block, SMEM128>>>(
        bufB, bufA, Wrest + 1 * G4 * H_D, Whh + 2 * G4 * H_D,
        bih + 2 * G4, bhh + 2 * G4);
    lstm_layer<H_D><<<grid, block, SMEM128>>>(
        bufA, bufB, Wrest + 2 * G4 * H_D, Whh + 3 * G4 * H_D,
        bih + 3 * G4, bhh + 3 * G4);
    lstm_layer<H_D><<<grid, block, SMEM128>>>(
        bufB, out, Wrest + 3 * G4 * H_D, Whh + 4 * G4 * H_D,
        bih + 4 * G4, bhh + 4 * G4);
}